// round 1
// baseline (speedup 1.0000x reference)
#include <cuda_runtime.h>
#include <cstdint>

// Problem constants (match reference)
#define BATCH 256
#define NSRC  10
#define NMC_C 16
#define LL_C  128

// ---------------------------------------------------------------------------
// Fill: out[b, ch, y, x] = (ch < nmc) ? 1.0f : 0.0f
// Channel plane = LL*LL = 16384 contiguous floats = 4096 float4s.
// For float4 index i: channel = (i >> 12) & 31. All 4 lanes same channel.
// ---------------------------------------------------------------------------
__global__ void fill_kernel(float4* __restrict__ out, long n4) {
    long i = (long)blockIdx.x * blockDim.x + threadIdx.x;
    if (i >= n4) return;
    float v = (((i >> 12) & 31) < NMC_C) ? 1.0f : 0.0f;
    out[i] = make_float4(v, v, v, v);
}

// ---------------------------------------------------------------------------
// Scatter: for each (b, src) triplet (x, y, mass):
//   xg = (x - lo0)/(hi0 - lo0); yg likewise; mg = (log10(mass) - lo2)/(hi2 - lo2)
//   xi = floor(xg*L), yi = floor(yg*L), mi = floor(mg*nmc)
//   out[b, mi, yi, xi]       = 0.0f   (1 - z half)
//   out[b, nmc+mi, yi, xi]   = 1.0f   (z half)
// OOB indices dropped (JAX scatter default).
// ---------------------------------------------------------------------------
__global__ void scatter_kernel(const float* __restrict__ coord,
                               const float* __restrict__ lows,
                               const float* __restrict__ highs,
                               float* __restrict__ out) {
    int t = blockIdx.x * blockDim.x + threadIdx.x;
    if (t >= BATCH * NSRC) return;
    int b = t / NSRC;
    int s = t - b * NSRC;

    const float* c = coord + (size_t)b * (3 * NSRC) + s * 3;
    float lo0 = lows[0], lo1 = lows[1], lo2 = lows[2];
    float hi0 = highs[0], hi1 = highs[1], hi2 = highs[2];

    float xg = (c[0]          - lo0) / (hi0 - lo0);
    float yg = (c[1]          - lo1) / (hi1 - lo1);
    float mg = (log10f(c[2])  - lo2) / (hi2 - lo2);

    int xi = (int)floorf(xg * (float)LL_C);
    int yi = (int)floorf(yg * (float)LL_C);
    int mi = (int)floorf(mg * (float)NMC_C);

    if ((unsigned)xi >= LL_C || (unsigned)yi >= LL_C || (unsigned)mi >= NMC_C)
        return;  // drop OOB like JAX scatter

    size_t plane = (size_t)LL_C * LL_C;
    size_t base  = (size_t)b * (2 * NMC_C) * plane + (size_t)yi * LL_C + xi;
    out[base + (size_t)mi * plane]            = 0.0f;
    out[base + (size_t)(NMC_C + mi) * plane]  = 1.0f;
}

extern "C" void kernel_launch(void* const* d_in, const int* in_sizes, int n_in,
                              void* d_out, int out_size) {
    const float* coord = (const float*)d_in[0];
    const float* lows  = (const float*)d_in[1];
    const float* highs = (const float*)d_in[2];
    float* out = (float*)d_out;

    long n4 = (long)out_size / 4;  // out_size = 256*32*128*128, divisible by 4
    int threads = 256;
    long blocks = (n4 + threads - 1) / threads;
    fill_kernel<<<(unsigned)blocks, threads>>>((float4*)out, n4);

    int npts = BATCH * NSRC;
    scatter_kernel<<<(npts + 255) / 256, 256>>>(coord, lows, highs, out);
}

// round 6
// speedup vs baseline: 1.0160x; 1.0160x over previous
#include <cuda_runtime.h>
#include <cstdint>

// Problem constants (match reference)
#define BATCH 256
#define NSRC  10
#define NMC_C 16
#define LL_C  128
#define PLANE (LL_C * LL_C)          // 16384 floats per channel plane
#define PLANE4 (PLANE / 4)           // 4096 float4 per plane

// One block per (batch, channel) plane. grid = BATCH * 2*NMC_C = 8192 blocks.
// Threads: 256. Each thread writes 16 coalesced float4 (one full plane/block).
// Threads 0..NSRC-1 additionally compute the scatter indices for this batch
// (overlapped with the DRAM-bound bulk stores of the other warps), then after
// __syncthreads() apply the <=10 per-plane overrides.
__global__ void __launch_bounds__(256) fused_kernel(
    const float* __restrict__ coord,
    const float* __restrict__ lows,
    const float* __restrict__ highs,
    float* __restrict__ out)
{
    __shared__ int s_idx[NSRC];   // packed mi*PLANE_ID? -> store (mi, yi*128+xi), -1 = OOB
    __shared__ int s_off[NSRC];

    int blk = blockIdx.x;
    int b   = blk >> 5;           // batch
    int ch  = blk & 31;           // channel 0..31
    int t   = threadIdx.x;

    // --- index computation (threads 0..9), overlapped with bulk stores ---
    if (t < NSRC) {
        const float* c = coord + (size_t)b * (3 * NSRC) + t * 3;
        float lo0 = lows[0], lo1 = lows[1], lo2 = lows[2];
        float hi0 = highs[0], hi1 = highs[1], hi2 = highs[2];

        float xg = (c[0]         - lo0) / (hi0 - lo0);
        float yg = (c[1]         - lo1) / (hi1 - lo1);
        float mg = (log10f(c[2]) - lo2) / (hi2 - lo2);

        int xi = (int)floorf(xg * (float)LL_C);
        int yi = (int)floorf(yg * (float)LL_C);
        int mi = (int)floorf(mg * (float)NMC_C);

        bool ok = ((unsigned)xi < LL_C) & ((unsigned)yi < LL_C) & ((unsigned)mi < NMC_C);
        s_idx[t] = ok ? mi : -1;
        s_off[t] = yi * LL_C + xi;
    }

    // --- bulk plane fill (all 256 threads, coalesced float4) ---
    float v = (ch < NMC_C) ? 1.0f : 0.0f;
    float4 vv = make_float4(v, v, v, v);
    float4* p = (float4*)(out + (size_t)blk * PLANE);
#pragma unroll
    for (int k = 0; k < PLANE4 / 256; k++) {
        p[t + k * 256] = vv;
    }

    __syncthreads();   // fences prior global writes within the block

    // --- apply overrides for points whose mass bin matches this channel ---
    if (t < NSRC) {
        int mi = s_idx[t];
        if (mi == (ch & (NMC_C - 1))) {
            // ch < NMC_C: this is the (1 - z) half -> 0; else z half -> 1
            out[(size_t)blk * PLANE + s_off[t]] = (ch < NMC_C) ? 0.0f : 1.0f;
        }
    }
}

extern "C" void kernel_launch(void* const* d_in, const int* in_sizes, int n_in,
                              void* d_out, int out_size) {
    const float* coord = (const float*)d_in[0];
    const float* lows  = (const float*)d_in[1];
    const float* highs = (const float*)d_in[2];
    float* out = (float*)d_out;

    fused_kernel<<<BATCH * 2 * NMC_C, 256>>>(coord, lows, highs, out);
}